// round 8
// baseline (speedup 1.0000x reference)
#include <cuda_runtime.h>
#include <math.h>

// ---------------- problem constants ----------------
constexpr int B  = 128;
constexpr int C  = 256;
constexpr int HW = 1024;          // 32*32
constexpr int N  = 2048;          // 2*HW tokens per batch
constexpr int D  = 64;
constexpr int S  = 8;
constexpr int MH = 128;
constexpr int NC = 15;
constexpr float LN_EPS = 1e-5f;
constexpr float SA_EPS = 1e-8f;

// ---------------- device scratch (static, allocation-free) ----------------
// k, v stored d-major: [b][d][n]  (n contiguous -> coalesced)
__device__ float g_k  [(size_t)B * D * N];     // 64 MB
__device__ float g_v  [(size_t)B * D * N];     // 64 MB
__device__ float g_slots[B * S * D];
__device__ float g_q    [B * S * D];
__device__ float g_colsum[B * S];
__device__ float g_upd  [B * S * D];           // numerators (divided in gru)

// =====================================================================
// K1: 1x1 conv (GEMM) + bias + LN(norm) + LN(ni) + k/v projection.
// grid: B*2*8 = 2048 CTAs, 256 threads. CTA = 128 tokens of one image/conv.
// writes g_k[b][d][n], g_v[b][d][n] directly (no token round-trip).
// =====================================================================
__global__ __launch_bounds__(256) void k_conv_kv(
    const float* __restrict__ x1, const float* __restrict__ x2,
    const float* __restrict__ cw1, const float* __restrict__ cb1,
    const float* __restrict__ cw2, const float* __restrict__ cb2,
    const float* __restrict__ nw,  const float* __restrict__ nb,
    const float* __restrict__ niw, const float* __restrict__ nib,
    const float* __restrict__ Wk,  const float* __restrict__ Wv)
{
    // tok_s doubles as the conv x-staging buffer (rows 0..31) during phase 1.
    __shared__ float tok_s[64][128];              // 32 KB
    __shared__ float wbuf[32][68];                // conv weights / kv weights (8.5 KB)
    __shared__ float s_m1[128], s_q1[128], s_m2[128], s_q2[128];
    __shared__ float p_nw[64], p_nb[64], p_iw[64], p_ib[64];

    float (*xs)[128] = tok_s;   // alias: conv phase uses rows 0..31

    const int t    = threadIdx.x;
    const int cid  = blockIdx.x;
    const int b    = cid >> 4;
    const int r    = cid & 15;
    const int conv = r >> 3;
    const int tile = r & 7;
    const int hw0  = tile * 128;

    const float* x    = (conv ? x2 : x1) + (size_t)b * C * HW + hw0;
    const float* w    = conv ? cw2 : cw1;
    const float* bias = conv ? cb2 : cb1;

    if (t < 64)  { p_nw[t] = nw[t]; p_nb[t] = nb[t]; p_iw[t] = niw[t]; p_ib[t] = nib[t]; }
    if (t < 128) { s_m1[t] = 0.f; s_q1[t] = 0.f; s_m2[t] = 0.f; s_q2[t] = 0.f; }

    const int dgrp = t >> 5, lane = t & 31;
    const int d0 = dgrp * 8, tk0 = lane * 4;

    float acc[8][4];
#pragma unroll
    for (int j = 0; j < 8; j++)
#pragma unroll
        for (int i = 0; i < 4; i++) acc[j][i] = 0.f;

    const float4* x4 = (const float4*)x;   // row stride HW/4 = 256 float4

    for (int c0 = 0; c0 < C; c0 += 32) {
        __syncthreads();
#pragma unroll
        for (int j = 0; j < 4; j++) {
            int e = t + 256 * j;            // 1024 float4 = 32 rows x 32 float4
            int row = e >> 5, c4 = e & 31;
            ((float4*)xs[row])[c4] = x4[(size_t)(c0 + row) * 256 + c4];
        }
#pragma unroll
        for (int j = 0; j < 8; j++) {
            int e = t + 256 * j;
            wbuf[e & 31][e >> 5] = w[(e >> 5) * C + c0 + (e & 31)];
        }
        __syncthreads();
#pragma unroll
        for (int cc = 0; cc < 32; cc++) {
            float4 xv = *(const float4*)&xs[cc][tk0];
            float4 wa = *(const float4*)&wbuf[cc][d0];
            float4 wb = *(const float4*)&wbuf[cc][d0 + 4];
            float wr[8] = {wa.x, wa.y, wa.z, wa.w, wb.x, wb.y, wb.z, wb.w};
#pragma unroll
            for (int j = 0; j < 8; j++) {
                acc[j][0] = fmaf(wr[j], xv.x, acc[j][0]);
                acc[j][1] = fmaf(wr[j], xv.y, acc[j][1]);
                acc[j][2] = fmaf(wr[j], xv.z, acc[j][2]);
                acc[j][3] = fmaf(wr[j], xv.w, acc[j][3]);
            }
        }
    }

    // bias
#pragma unroll
    for (int j = 0; j < 8; j++) {
        float bb = __ldg(&bias[d0 + j]);
#pragma unroll
        for (int i = 0; i < 4; i++) acc[j][i] += bb;
    }
    __syncthreads();          // all xs reads complete here
    // LN1 stats
#pragma unroll
    for (int i = 0; i < 4; i++) {
        float ps = 0.f, pq = 0.f;
#pragma unroll
        for (int j = 0; j < 8; j++) { ps += acc[j][i]; pq += acc[j][i] * acc[j][i]; }
        atomicAdd(&s_m1[tk0 + i], ps);
        atomicAdd(&s_q1[tk0 + i], pq);
    }
    __syncthreads();
    // apply LN1, accumulate LN2 stats
#pragma unroll
    for (int i = 0; i < 4; i++) {
        float mu = s_m1[tk0 + i] * (1.f / 64.f);
        float var = s_q1[tk0 + i] * (1.f / 64.f) - mu * mu;
        float rs = rsqrtf(var + LN_EPS);
        float ps = 0.f, pq = 0.f;
#pragma unroll
        for (int j = 0; j < 8; j++) {
            float v = (acc[j][i] - mu) * rs * p_nw[d0 + j] + p_nb[d0 + j];
            acc[j][i] = v;
            ps += v; pq += v * v;
        }
        atomicAdd(&s_m2[tk0 + i], ps);
        atomicAdd(&s_q2[tk0 + i], pq);
    }
    __syncthreads();
    float mu2[4], rs2[4];
#pragma unroll
    for (int i = 0; i < 4; i++) {
        float m = s_m2[tk0 + i] * (1.f / 64.f);
        float v = s_q2[tk0 + i] * (1.f / 64.f) - m * m;
        mu2[i] = m; rs2[i] = rsqrtf(v + LN_EPS);
    }
    // write LN2'd tokens into tok_s[d][token]
#pragma unroll
    for (int j = 0; j < 8; j++) {
        float ww = p_iw[d0 + j], bb = p_ib[d0 + j];
        float4 o;
        o.x = (acc[j][0] - mu2[0]) * rs2[0] * ww + bb;
        o.y = (acc[j][1] - mu2[1]) * rs2[1] * ww + bb;
        o.z = (acc[j][2] - mu2[2]) * rs2[2] * ww + bb;
        o.w = (acc[j][3] - mu2[3]) * rs2[3] * ww + bb;
        *(float4*)&tok_s[d0 + j][tk0] = o;
    }

    // ---------------- kv phase: k = tok @ Wk^T, v = tok @ Wv^T ----------------
    float ka[8][4], va[8][4];
#pragma unroll
    for (int j = 0; j < 8; j++)
#pragma unroll
        for (int i = 0; i < 4; i++) { ka[j][i] = 0.f; va[j][i] = 0.f; }

    for (int c0 = 0; c0 < 64; c0 += 16) {
        __syncthreads();    // protects wbuf reuse (and tok_s writes on first pass)
#pragma unroll
        for (int j = 0; j < 4; j++) {
            int e = t + 256 * j;            // 1024 entries: d=e>>4 (0..63), cc=e&15
            int d = e >> 4, cc = e & 15;
            wbuf[cc][d]      = Wk[d * 64 + c0 + cc];
            wbuf[16 + cc][d] = Wv[d * 64 + c0 + cc];
        }
        __syncthreads();
#pragma unroll
        for (int cc = 0; cc < 16; cc++) {
            float4 xv  = *(const float4*)&tok_s[c0 + cc][tk0];
            float4 ka4 = *(const float4*)&wbuf[cc][d0];
            float4 kb4 = *(const float4*)&wbuf[cc][d0 + 4];
            float4 va4 = *(const float4*)&wbuf[16 + cc][d0];
            float4 vb4 = *(const float4*)&wbuf[16 + cc][d0 + 4];
            float kr[8] = {ka4.x, ka4.y, ka4.z, ka4.w, kb4.x, kb4.y, kb4.z, kb4.w};
            float vr[8] = {va4.x, va4.y, va4.z, va4.w, vb4.x, vb4.y, vb4.z, vb4.w};
#pragma unroll
            for (int j = 0; j < 8; j++) {
                ka[j][0] = fmaf(kr[j], xv.x, ka[j][0]);
                ka[j][1] = fmaf(kr[j], xv.y, ka[j][1]);
                ka[j][2] = fmaf(kr[j], xv.z, ka[j][2]);
                ka[j][3] = fmaf(kr[j], xv.w, ka[j][3]);
                va[j][0] = fmaf(vr[j], xv.x, va[j][0]);
                va[j][1] = fmaf(vr[j], xv.y, va[j][1]);
                va[j][2] = fmaf(vr[j], xv.z, va[j][2]);
                va[j][3] = fmaf(vr[j], xv.w, va[j][3]);
            }
        }
    }
    const int n0 = conv * HW + hw0;
    float* kp = g_k + (size_t)b * D * N + n0;
    float* vp = g_v + (size_t)b * D * N + n0;
#pragma unroll
    for (int j = 0; j < 8; j++) {
        float4 ok = {ka[j][0], ka[j][1], ka[j][2], ka[j][3]};
        float4 ov = {va[j][0], va[j][1], va[j][2], va[j][3]};
        *(float4*)&kp[(size_t)(d0 + j) * N + tk0] = ok;
        *(float4*)&vp[(size_t)(d0 + j) * N + tk0] = ov;
    }
}

// =====================================================================
// K2: slots init + LN(ns) + q for iteration 0; zeroes colsum/upd.
// grid B, 256 threads.
// =====================================================================
__global__ __launch_bounds__(256) void k_init_q(
    const float* __restrict__ mu_, const float* __restrict__ ls,
    const float* __restrict__ noise, const float* __restrict__ Wq,
    const float* __restrict__ nsw, const float* __restrict__ nsb)
{
    __shared__ float ws[32][65];
    __shared__ float lns[8][64];
    const int t = threadIdx.x, b = blockIdx.x;
    const int w = t >> 5, lane = t & 31;

    {
        int d = t & 63;
        g_slots[b * 512 + t]       = mu_[d] + expf(ls[d]) * noise[b * 512 + t];
        g_slots[b * 512 + t + 256] = mu_[d] + expf(ls[d]) * noise[b * 512 + t + 256];
    }
    if (t < 8) g_colsum[b * 8 + t] = 0.f;
    g_upd[b * 512 + t] = 0.f;
    g_upd[b * 512 + t + 256] = 0.f;
    __syncthreads();

    float v0 = g_slots[b * 512 + w * 64 + lane];
    float v1 = g_slots[b * 512 + w * 64 + lane + 32];
    float s = v0 + v1, q2 = v0 * v0 + v1 * v1;
#pragma unroll
    for (int o = 16; o > 0; o >>= 1) {
        s  += __shfl_xor_sync(~0u, s, o);
        q2 += __shfl_xor_sync(~0u, q2, o);
    }
    float mu = s * (1.f / 64.f);
    float rs = rsqrtf(q2 * (1.f / 64.f) - mu * mu + LN_EPS);
    lns[w][lane]      = (v0 - mu) * rs * __ldg(&nsw[lane])      + __ldg(&nsb[lane]);
    lns[w][lane + 32] = (v1 - mu) * rs * __ldg(&nsw[lane + 32]) + __ldg(&nsb[lane + 32]);

    for (int c = 0; c < 64; c += 32) {
        __syncthreads();
#pragma unroll
        for (int j = 0; j < 8; j++) {
            int e = t + 256 * j;
            ws[e >> 6][e & 63] = Wq[(c + (e >> 6)) * 64 + (e & 63)];
        }
        __syncthreads();
        float a = 0.f;
#pragma unroll
        for (int din = 0; din < 64; din++)
            a = fmaf(lns[w][din], ws[lane][din], a);
        g_q[b * 512 + w * 64 + c + lane] = a * 0.125f;
    }
}

// =====================================================================
// K3: attn (softmax over S) + partial colsum + partial updates numerator.
// grid B*8 (256 tokens per CTA), 256 threads.
// =====================================================================
__global__ __launch_bounds__(256) void k_attn_upd(void)
{
    __shared__ float qs[512];
    __shared__ float as_[256][9];
    __shared__ float scs[8];
    const int t = threadIdx.x;
    const int b = blockIdx.x >> 3;
    const int n0 = (blockIdx.x & 7) * 256;
    const int w = t >> 5, lane = t & 31;

    if (t < 8) scs[t] = 0.f;
    qs[t] = g_q[b * 512 + t];
    qs[t + 256] = g_q[b * 512 + t + 256];
    __syncthreads();

    const float* kb = g_k + (size_t)b * D * N + n0 + t;
    float lg[8];
#pragma unroll
    for (int s = 0; s < 8; s++) lg[s] = 0.f;
#pragma unroll 8
    for (int d = 0; d < 64; d++) {
        float kv = kb[(size_t)d * N];
#pragma unroll
        for (int s = 0; s < 8; s++) lg[s] = fmaf(kv, qs[s * 64 + d], lg[s]);
    }
    float m = lg[0];
#pragma unroll
    for (int s = 1; s < 8; s++) m = fmaxf(m, lg[s]);
    float sum = 0.f;
#pragma unroll
    for (int s = 0; s < 8; s++) { lg[s] = expf(lg[s] - m); sum += lg[s]; }
    float inv = 1.f / sum;
#pragma unroll
    for (int s = 0; s < 8; s++) {
        lg[s] = lg[s] * inv + SA_EPS;
        as_[t][s] = lg[s];
    }

    // partial colsum
#pragma unroll
    for (int s = 0; s < 8; s++) {
        float v = lg[s];
#pragma unroll
        for (int o = 16; o > 0; o >>= 1) v += __shfl_xor_sync(~0u, v, o);
        if (lane == 0) atomicAdd(&scs[s], v);
    }
    __syncthreads();
    if (t < 8) atomicAdd(&g_colsum[b * 8 + t], scs[t]);

    // partial updates numerator: warp w owns d = w*8 .. w*8+7
    float acc[8][8];
#pragma unroll
    for (int j = 0; j < 8; j++)
#pragma unroll
        for (int s = 0; s < 8; s++) acc[j][s] = 0.f;

    const float* vb = g_v + (size_t)b * D * N + n0;
#pragma unroll
    for (int it = 0; it < 8; it++) {
        int n = it * 32 + lane;
        float ar[8];
#pragma unroll
        for (int s = 0; s < 8; s++) ar[s] = as_[n][s];
#pragma unroll
        for (int j = 0; j < 8; j++) {
            float vv = vb[(size_t)(w * 8 + j) * N + n];
#pragma unroll
            for (int s = 0; s < 8; s++) acc[j][s] = fmaf(vv, ar[s], acc[j][s]);
        }
    }
#pragma unroll
    for (int j = 0; j < 8; j++) {
#pragma unroll
        for (int s = 0; s < 8; s++) {
            float v = acc[j][s];
#pragma unroll
            for (int o = 16; o > 0; o >>= 1) v += __shfl_xor_sync(~0u, v, o);
            if (lane == s)
                atomicAdd(&g_upd[b * 512 + s * 64 + w * 8 + j], v);
        }
    }
}

// =====================================================================
// K4: GRU + residual MLP -> new slots, then LN(ns)+q for next iteration.
// Divides update numerators by colsum; zeroes colsum/upd for next iter.
// grid B, 256 threads.
// =====================================================================
__global__ __launch_bounds__(256) void k_gru_mlp_q(
    const float* __restrict__ wih, const float* __restrict__ whh,
    const float* __restrict__ bih, const float* __restrict__ bhh,
    const float* __restrict__ nmw, const float* __restrict__ nmb,
    const float* __restrict__ mw1, const float* __restrict__ mb1,
    const float* __restrict__ mw2, const float* __restrict__ mb2,
    const float* __restrict__ Wq,
    const float* __restrict__ nsw, const float* __restrict__ nsb)
{
    __shared__ float us[8][64], sp[8][64];
    __shared__ float gih[8][192], ghh[8][192];
    __shared__ float ws1[32][65], ws2[32][65];
    __shared__ float lns[8][64];
    __shared__ float h1s[8][128];

    const int t = threadIdx.x, b = blockIdx.x;
    const int w = t >> 5, lane = t & 31;

    {
        float cs0 = g_colsum[b * 8 + (t >> 6)];
        float cs1 = g_colsum[b * 8 + ((t + 256) >> 6)];
        ((float*)us)[t]       = g_upd[b * 512 + t] / cs0;
        ((float*)us)[t + 256] = g_upd[b * 512 + t + 256] / cs1;
    }
    ((float*)sp)[t]       = g_slots[b * 512 + t];
    ((float*)sp)[t + 256] = g_slots[b * 512 + t + 256];
    __syncthreads();
    // reset accumulators for next iteration
    if (t < 8) g_colsum[b * 8 + t] = 0.f;
    g_upd[b * 512 + t] = 0.f;
    g_upd[b * 512 + t + 256] = 0.f;

    // gi / gh : 6 chunks of 32 outputs
    for (int c = 0; c < 6; c++) {
        const int o0 = c * 32;
        __syncthreads();
#pragma unroll
        for (int j = 0; j < 8; j++) {
            int e = t + 256 * j;
            int oo = e >> 6, din = e & 63;
            ws1[oo][din] = wih[(o0 + oo) * 64 + din];
            ws2[oo][din] = whh[(o0 + oo) * 64 + din];
        }
        __syncthreads();
        float a = __ldg(&bih[o0 + lane]);
        float h = __ldg(&bhh[o0 + lane]);
#pragma unroll
        for (int din = 0; din < 64; din++) {
            a = fmaf(us[w][din], ws1[lane][din], a);
            h = fmaf(sp[w][din], ws2[lane][din], h);
        }
        gih[w][o0 + lane] = a;
        ghh[w][o0 + lane] = h;
    }
    __syncthreads();

    // gates (torch order r,z,n)
    float sn0, sn1;
    {
        int dd = lane;
        float r = 1.f / (1.f + expf(-(gih[w][dd] + ghh[w][dd])));
        float z = 1.f / (1.f + expf(-(gih[w][64 + dd] + ghh[w][64 + dd])));
        float nn = tanhf(gih[w][128 + dd] + r * ghh[w][128 + dd]);
        sn0 = (1.f - z) * nn + z * sp[w][dd];
    }
    {
        int dd = lane + 32;
        float r = 1.f / (1.f + expf(-(gih[w][dd] + ghh[w][dd])));
        float z = 1.f / (1.f + expf(-(gih[w][64 + dd] + ghh[w][64 + dd])));
        float nn = tanhf(gih[w][128 + dd] + r * ghh[w][128 + dd]);
        sn1 = (1.f - z) * nn + z * sp[w][dd];
    }
    // LN(nm) of GRU output
    float s = sn0 + sn1, q2 = sn0 * sn0 + sn1 * sn1;
#pragma unroll
    for (int o = 16; o > 0; o >>= 1) {
        s  += __shfl_xor_sync(~0u, s, o);
        q2 += __shfl_xor_sync(~0u, q2, o);
    }
    float mu = s * (1.f / 64.f);
    float rs = rsqrtf(q2 * (1.f / 64.f) - mu * mu + LN_EPS);
    lns[w][lane]      = (sn0 - mu) * rs * __ldg(&nmw[lane])      + __ldg(&nmb[lane]);
    lns[w][lane + 32] = (sn1 - mu) * rs * __ldg(&nmw[lane + 32]) + __ldg(&nmb[lane + 32]);
    __syncthreads();

    // MLP layer 1: 4 chunks of 32 hidden units
    for (int c = 0; c < 4; c++) {
        const int m0 = c * 32;
        __syncthreads();
#pragma unroll
        for (int j = 0; j < 8; j++) {
            int e = t + 256 * j;
            int mm = e >> 6, din = e & 63;
            ws1[mm][din] = mw1[(m0 + mm) * 64 + din];
        }
        __syncthreads();
        float a = __ldg(&mb1[m0 + lane]);
#pragma unroll
        for (int din = 0; din < 64; din++)
            a = fmaf(lns[w][din], ws1[lane][din], a);
        h1s[w][m0 + lane] = fmaxf(a, 0.f);
    }
    __syncthreads();

    // MLP layer 2
    float out0 = __ldg(&mb2[lane]);
    float out1 = __ldg(&mb2[lane + 32]);
    for (int c = 0; c < 4; c++) {
        const int m0 = c * 32;
        __syncthreads();
#pragma unroll
        for (int j = 0; j < 8; j++) {
            int e = t + 256 * j;               // d = e>>5 (0..63), mm = e&31
            ws1[e & 31][e >> 5] = mw2[(e >> 5) * 128 + m0 + (e & 31)];
        }
        __syncthreads();
#pragma unroll
        for (int mm = 0; mm < 32; mm++) {
            float hv = h1s[w][m0 + mm];
            out0 = fmaf(hv, ws1[mm][lane], out0);
            out1 = fmaf(hv, ws1[mm][lane + 32], out1);
        }
    }
    float fs0 = sn0 + out0, fs1 = sn1 + out1;
    g_slots[b * 512 + w * 64 + lane]      = fs0;
    g_slots[b * 512 + w * 64 + lane + 32] = fs1;

    // ---- q for NEXT iteration: LN(ns) + @ Wq^T * scale ----
    float s2 = fs0 + fs1, qq = fs0 * fs0 + fs1 * fs1;
#pragma unroll
    for (int o = 16; o > 0; o >>= 1) {
        s2 += __shfl_xor_sync(~0u, s2, o);
        qq += __shfl_xor_sync(~0u, qq, o);
    }
    float mu3 = s2 * (1.f / 64.f);
    float rs3 = rsqrtf(qq * (1.f / 64.f) - mu3 * mu3 + LN_EPS);
    __syncthreads();   // before lns reuse
    lns[w][lane]      = (fs0 - mu3) * rs3 * __ldg(&nsw[lane])      + __ldg(&nsb[lane]);
    lns[w][lane + 32] = (fs1 - mu3) * rs3 * __ldg(&nsw[lane + 32]) + __ldg(&nsb[lane + 32]);

    for (int c = 0; c < 64; c += 32) {
        __syncthreads();
#pragma unroll
        for (int j = 0; j < 8; j++) {
            int e = t + 256 * j;
            ws1[e >> 6][e & 63] = Wq[(c + (e >> 6)) * 64 + (e & 63)];
        }
        __syncthreads();
        float a = 0.f;
#pragma unroll
        for (int din = 0; din < 64; din++)
            a = fmaf(lns[w][din], ws1[lane][din], a);
        g_q[b * 512 + w * 64 + c + lane] = a * 0.125f;
    }
}

// =====================================================================
// K5: fused = mean(slots, axis=S); out = fused @ head_w^T + head_b
// grid B, 64 threads.
// =====================================================================
__global__ void k_head(const float* __restrict__ hw_, const float* __restrict__ hb_,
                       float* __restrict__ out)
{
    __shared__ float f[64];
    const int t = threadIdx.x, b = blockIdx.x;
    float s = 0.f;
#pragma unroll
    for (int ss = 0; ss < 8; ss++) s += g_slots[b * 512 + ss * 64 + t];
    f[t] = s * (1.f / 8.f);
    __syncthreads();
    if (t < NC) {
        float a = hb_[t];
#pragma unroll
        for (int d = 0; d < 64; d++) a = fmaf(f[d], hw_[t * 64 + d], a);
        out[b * NC + t] = a;
    }
}

// =====================================================================
extern "C" void kernel_launch(void* const* d_in, const int* in_sizes, int n_in,
                              void* d_out, int out_size)
{
    const float* x1   = (const float*)d_in[0];
    const float* x2   = (const float*)d_in[1];
    const float* c1w  = (const float*)d_in[2];
    const float* c1b  = (const float*)d_in[3];
    const float* c2w  = (const float*)d_in[4];
    const float* c2b  = (const float*)d_in[5];
    const float* nw   = (const float*)d_in[6];
    const float* nb   = (const float*)d_in[7];
    const float* niw  = (const float*)d_in[8];
    const float* nib  = (const float*)d_in[9];
    const float* nsw  = (const float*)d_in[10];
    const float* nsb  = (const float*)d_in[11];
    const float* nmw  = (const float*)d_in[12];
    const float* nmb  = (const float*)d_in[13];
    const float* smu  = (const float*)d_in[14];
    const float* sls  = (const float*)d_in[15];
    const float* Wq   = (const float*)d_in[16];
    const float* Wk   = (const float*)d_in[17];
    const float* Wv   = (const float*)d_in[18];
    const float* wih  = (const float*)d_in[19];
    const float* whh  = (const float*)d_in[20];
    const float* bih  = (const float*)d_in[21];
    const float* bhh  = (const float*)d_in[22];
    const float* mw1  = (const float*)d_in[23];
    const float* mb1  = (const float*)d_in[24];
    const float* mw2  = (const float*)d_in[25];
    const float* mb2  = (const float*)d_in[26];
    const float* hw_  = (const float*)d_in[27];
    const float* hb_  = (const float*)d_in[28];
    const float* noise= (const float*)d_in[29];
    float* out = (float*)d_out;

    k_conv_kv<<<B * 16, 256>>>(x1, x2, c1w, c1b, c2w, c2b, nw, nb, niw, nib, Wk, Wv);
    k_init_q<<<B, 256>>>(smu, sls, noise, Wq, nsw, nsb);

    for (int it = 0; it < 3; it++) {
        k_attn_upd<<<B * 8, 256>>>();
        k_gru_mlp_q<<<B, 256>>>(wih, whh, bih, bhh, nmw, nmb,
                                mw1, mb1, mw2, mb2, Wq, nsw, nsb);
    }
    k_head<<<B, 64>>>(hw_, hb_, out);
}

// round 9
// speedup vs baseline: 1.0334x; 1.0334x over previous
#include <cuda_runtime.h>
#include <math.h>

// ---------------- problem constants ----------------
constexpr int B  = 128;
constexpr int C  = 256;
constexpr int HW = 1024;          // 32*32
constexpr int N  = 2048;          // 2*HW tokens per batch
constexpr int D  = 64;
constexpr int S  = 8;
constexpr int MH = 128;
constexpr int NC = 15;
constexpr float LN_EPS = 1e-5f;
constexpr float SA_EPS = 1e-8f;

// ---------------- device scratch (static, allocation-free) ----------------
// k, v stored d-major: [b][d][n]  (n contiguous -> coalesced)
__device__ float g_k  [(size_t)B * D * N];     // 64 MB
__device__ float g_v  [(size_t)B * D * N];     // 64 MB
__device__ float g_slots[B * S * D];
__device__ float g_q    [B * S * D];
__device__ float g_colsum[B * S];
__device__ float g_upd  [B * S * D];           // numerators (divided in gru)

// =====================================================================
// K1: 1x1 conv (GEMM) + bias + LN(norm) + LN(ni) + k/v projection.
// grid: B*2*8 = 2048 CTAs, 256 threads. CTA = 128 tokens of one image/conv.
// writes g_k[b][d][n], g_v[b][d][n] directly (no token round-trip).
// =====================================================================
__global__ __launch_bounds__(256) void k_conv_kv(
    const float* __restrict__ x1, const float* __restrict__ x2,
    const float* __restrict__ cw1, const float* __restrict__ cb1,
    const float* __restrict__ cw2, const float* __restrict__ cb2,
    const float* __restrict__ nw,  const float* __restrict__ nb,
    const float* __restrict__ niw, const float* __restrict__ nib,
    const float* __restrict__ Wk,  const float* __restrict__ Wv)
{
    // tok_s doubles as the conv x-staging buffer (rows 0..31) during phase 1.
    __shared__ float tok_s[64][128];              // 32 KB
    __shared__ float wbuf[32][68];                // conv weights / kv weights (8.5 KB)
    __shared__ float s_m1[128], s_q1[128], s_m2[128], s_q2[128];
    __shared__ float p_nw[64], p_nb[64], p_iw[64], p_ib[64];

    float (*xs)[128] = tok_s;   // alias: conv phase uses rows 0..31

    const int t    = threadIdx.x;
    const int cid  = blockIdx.x;
    const int b    = cid >> 4;
    const int r    = cid & 15;
    const int conv = r >> 3;
    const int tile = r & 7;
    const int hw0  = tile * 128;

    const float* x    = (conv ? x2 : x1) + (size_t)b * C * HW + hw0;
    const float* w    = conv ? cw2 : cw1;
    const float* bias = conv ? cb2 : cb1;

    if (t < 64)  { p_nw[t] = nw[t]; p_nb[t] = nb[t]; p_iw[t] = niw[t]; p_ib[t] = nib[t]; }
    if (t < 128) { s_m1[t] = 0.f; s_q1[t] = 0.f; s_m2[t] = 0.f; s_q2[t] = 0.f; }

    const int dgrp = t >> 5, lane = t & 31;
    const int d0 = dgrp * 8, tk0 = lane * 4;

    float acc[8][4];
#pragma unroll
    for (int j = 0; j < 8; j++)
#pragma unroll
        for (int i = 0; i < 4; i++) acc[j][i] = 0.f;

    const float4* x4 = (const float4*)x;   // row stride HW/4 = 256 float4

    for (int c0 = 0; c0 < C; c0 += 32) {
        __syncthreads();
#pragma unroll
        for (int j = 0; j < 4; j++) {
            int e = t + 256 * j;            // 1024 float4 = 32 rows x 32 float4
            int row = e >> 5, c4 = e & 31;
            ((float4*)xs[row])[c4] = x4[(size_t)(c0 + row) * 256 + c4];
        }
#pragma unroll
        for (int j = 0; j < 8; j++) {
            int e = t + 256 * j;
            wbuf[e & 31][e >> 5] = w[(e >> 5) * C + c0 + (e & 31)];
        }
        __syncthreads();
#pragma unroll
        for (int cc = 0; cc < 32; cc++) {
            float4 xv = *(const float4*)&xs[cc][tk0];
            float4 wa = *(const float4*)&wbuf[cc][d0];
            float4 wb = *(const float4*)&wbuf[cc][d0 + 4];
            float wr[8] = {wa.x, wa.y, wa.z, wa.w, wb.x, wb.y, wb.z, wb.w};
#pragma unroll
            for (int j = 0; j < 8; j++) {
                acc[j][0] = fmaf(wr[j], xv.x, acc[j][0]);
                acc[j][1] = fmaf(wr[j], xv.y, acc[j][1]);
                acc[j][2] = fmaf(wr[j], xv.z, acc[j][2]);
                acc[j][3] = fmaf(wr[j], xv.w, acc[j][3]);
            }
        }
    }

    // bias
#pragma unroll
    for (int j = 0; j < 8; j++) {
        float bb = __ldg(&bias[d0 + j]);
#pragma unroll
        for (int i = 0; i < 4; i++) acc[j][i] += bb;
    }
    __syncthreads();          // all xs reads complete here
    // LN1 stats
#pragma unroll
    for (int i = 0; i < 4; i++) {
        float ps = 0.f, pq = 0.f;
#pragma unroll
        for (int j = 0; j < 8; j++) { ps += acc[j][i]; pq += acc[j][i] * acc[j][i]; }
        atomicAdd(&s_m1[tk0 + i], ps);
        atomicAdd(&s_q1[tk0 + i], pq);
    }
    __syncthreads();
    // apply LN1, accumulate LN2 stats
#pragma unroll
    for (int i = 0; i < 4; i++) {
        float mu = s_m1[tk0 + i] * (1.f / 64.f);
        float var = s_q1[tk0 + i] * (1.f / 64.f) - mu * mu;
        float rs = rsqrtf(var + LN_EPS);
        float ps = 0.f, pq = 0.f;
#pragma unroll
        for (int j = 0; j < 8; j++) {
            float v = (acc[j][i] - mu) * rs * p_nw[d0 + j] + p_nb[d0 + j];
            acc[j][i] = v;
            ps += v; pq += v * v;
        }
        atomicAdd(&s_m2[tk0 + i], ps);
        atomicAdd(&s_q2[tk0 + i], pq);
    }
    __syncthreads();
    float mu2[4], rs2[4];
#pragma unroll
    for (int i = 0; i < 4; i++) {
        float m = s_m2[tk0 + i] * (1.f / 64.f);
        float v = s_q2[tk0 + i] * (1.f / 64.f) - m * m;
        mu2[i] = m; rs2[i] = rsqrtf(v + LN_EPS);
    }
    // write LN2'd tokens into tok_s[d][token]
#pragma unroll
    for (int j = 0; j < 8; j++) {
        float ww = p_iw[d0 + j], bb = p_ib[d0 + j];
        float4 o;
        o.x = (acc[j][0] - mu2[0]) * rs2[0] * ww + bb;
        o.y = (acc[j][1] - mu2[1]) * rs2[1] * ww + bb;
        o.z = (acc[j][2] - mu2[2]) * rs2[2] * ww + bb;
        o.w = (acc[j][3] - mu2[3]) * rs2[3] * ww + bb;
        *(float4*)&tok_s[d0 + j][tk0] = o;
    }

    // ---------------- kv phase: k = tok @ Wk^T, v = tok @ Wv^T ----------------
    float ka[8][4], va[8][4];
#pragma unroll
    for (int j = 0; j < 8; j++)
#pragma unroll
        for (int i = 0; i < 4; i++) { ka[j][i] = 0.f; va[j][i] = 0.f; }

    for (int c0 = 0; c0 < 64; c0 += 16) {
        __syncthreads();    // protects wbuf reuse (and tok_s writes on first pass)
#pragma unroll
        for (int j = 0; j < 4; j++) {
            int e = t + 256 * j;            // 1024 entries: d=e>>4 (0..63), cc=e&15
            int d = e >> 4, cc = e & 15;
            wbuf[cc][d]      = Wk[d * 64 + c0 + cc];
            wbuf[16 + cc][d] = Wv[d * 64 + c0 + cc];
        }
        __syncthreads();
#pragma unroll
        for (int cc = 0; cc < 16; cc++) {
            float4 xv  = *(const float4*)&tok_s[c0 + cc][tk0];
            float4 ka4 = *(const float4*)&wbuf[cc][d0];
            float4 kb4 = *(const float4*)&wbuf[cc][d0 + 4];
            float4 va4 = *(const float4*)&wbuf[16 + cc][d0];
            float4 vb4 = *(const float4*)&wbuf[16 + cc][d0 + 4];
            float kr[8] = {ka4.x, ka4.y, ka4.z, ka4.w, kb4.x, kb4.y, kb4.z, kb4.w};
            float vr[8] = {va4.x, va4.y, va4.z, va4.w, vb4.x, vb4.y, vb4.z, vb4.w};
#pragma unroll
            for (int j = 0; j < 8; j++) {
                ka[j][0] = fmaf(kr[j], xv.x, ka[j][0]);
                ka[j][1] = fmaf(kr[j], xv.y, ka[j][1]);
                ka[j][2] = fmaf(kr[j], xv.z, ka[j][2]);
                ka[j][3] = fmaf(kr[j], xv.w, ka[j][3]);
                va[j][0] = fmaf(vr[j], xv.x, va[j][0]);
                va[j][1] = fmaf(vr[j], xv.y, va[j][1]);
                va[j][2] = fmaf(vr[j], xv.z, va[j][2]);
                va[j][3] = fmaf(vr[j], xv.w, va[j][3]);
            }
        }
    }
    const int n0 = conv * HW + hw0;
    float* kp = g_k + (size_t)b * D * N + n0;
    float* vp = g_v + (size_t)b * D * N + n0;
#pragma unroll
    for (int j = 0; j < 8; j++) {
        float4 ok = {ka[j][0], ka[j][1], ka[j][2], ka[j][3]};
        float4 ov = {va[j][0], va[j][1], va[j][2], va[j][3]};
        *(float4*)&kp[(size_t)(d0 + j) * N + tk0] = ok;
        *(float4*)&vp[(size_t)(d0 + j) * N + tk0] = ov;
    }
}

// =====================================================================
// K2: slots init + LN(ns) + q for iteration 0; zeroes colsum/upd.
// grid B, 256 threads.
// =====================================================================
__global__ __launch_bounds__(256) void k_init_q(
    const float* __restrict__ mu_, const float* __restrict__ ls,
    const float* __restrict__ noise, const float* __restrict__ Wq,
    const float* __restrict__ nsw, const float* __restrict__ nsb)
{
    __shared__ float ws[32][65];
    __shared__ float lns[8][64];
    const int t = threadIdx.x, b = blockIdx.x;
    const int w = t >> 5, lane = t & 31;

    {
        int d = t & 63;
        g_slots[b * 512 + t]       = mu_[d] + expf(ls[d]) * noise[b * 512 + t];
        g_slots[b * 512 + t + 256] = mu_[d] + expf(ls[d]) * noise[b * 512 + t + 256];
    }
    if (t < 8) g_colsum[b * 8 + t] = 0.f;
    g_upd[b * 512 + t] = 0.f;
    g_upd[b * 512 + t + 256] = 0.f;
    __syncthreads();

    float v0 = g_slots[b * 512 + w * 64 + lane];
    float v1 = g_slots[b * 512 + w * 64 + lane + 32];
    float s = v0 + v1, q2 = v0 * v0 + v1 * v1;
#pragma unroll
    for (int o = 16; o > 0; o >>= 1) {
        s  += __shfl_xor_sync(~0u, s, o);
        q2 += __shfl_xor_sync(~0u, q2, o);
    }
    float mu = s * (1.f / 64.f);
    float rs = rsqrtf(q2 * (1.f / 64.f) - mu * mu + LN_EPS);
    lns[w][lane]      = (v0 - mu) * rs * __ldg(&nsw[lane])      + __ldg(&nsb[lane]);
    lns[w][lane + 32] = (v1 - mu) * rs * __ldg(&nsw[lane + 32]) + __ldg(&nsb[lane + 32]);

    for (int c = 0; c < 64; c += 32) {
        __syncthreads();
#pragma unroll
        for (int j = 0; j < 8; j++) {
            int e = t + 256 * j;
            ws[e >> 6][e & 63] = Wq[(c + (e >> 6)) * 64 + (e & 63)];
        }
        __syncthreads();
        float a = 0.f;
#pragma unroll
        for (int din = 0; din < 64; din++)
            a = fmaf(lns[w][din], ws[lane][din], a);
        g_q[b * 512 + w * 64 + c + lane] = a * 0.125f;
    }
}

// =====================================================================
// K3: attn (softmax over S) + partial colsum + partial updates numerator.
// grid B*8 (256 tokens per CTA), 256 threads.
// =====================================================================
__global__ __launch_bounds__(256) void k_attn_upd(void)
{
    __shared__ float qs[512];
    __shared__ float as_[256][9];
    __shared__ float scs[8];
    const int t = threadIdx.x;
    const int b = blockIdx.x >> 3;
    const int n0 = (blockIdx.x & 7) * 256;
    const int w = t >> 5, lane = t & 31;

    if (t < 8) scs[t] = 0.f;
    qs[t] = g_q[b * 512 + t];
    qs[t + 256] = g_q[b * 512 + t + 256];
    __syncthreads();

    const float* kb = g_k + (size_t)b * D * N + n0 + t;
    float lg[8];
#pragma unroll
    for (int s = 0; s < 8; s++) lg[s] = 0.f;
#pragma unroll 8
    for (int d = 0; d < 64; d++) {
        float kv = kb[(size_t)d * N];
#pragma unroll
        for (int s = 0; s < 8; s++) lg[s] = fmaf(kv, qs[s * 64 + d], lg[s]);
    }
    float m = lg[0];
#pragma unroll
    for (int s = 1; s < 8; s++) m = fmaxf(m, lg[s]);
    float sum = 0.f;
#pragma unroll
    for (int s = 0; s < 8; s++) { lg[s] = expf(lg[s] - m); sum += lg[s]; }
    float inv = 1.f / sum;
#pragma unroll
    for (int s = 0; s < 8; s++) {
        lg[s] = lg[s] * inv + SA_EPS;
        as_[t][s] = lg[s];
    }

    // partial colsum
#pragma unroll
    for (int s = 0; s < 8; s++) {
        float v = lg[s];
#pragma unroll
        for (int o = 16; o > 0; o >>= 1) v += __shfl_xor_sync(~0u, v, o);
        if (lane == 0) atomicAdd(&scs[s], v);
    }
    __syncthreads();
    if (t < 8) atomicAdd(&g_colsum[b * 8 + t], scs[t]);

    // partial updates numerator: warp w owns d = w*8 .. w*8+7
    float acc[8][8];
#pragma unroll
    for (int j = 0; j < 8; j++)
#pragma unroll
        for (int s = 0; s < 8; s++) acc[j][s] = 0.f;

    const float* vb = g_v + (size_t)b * D * N + n0;
#pragma unroll
    for (int it = 0; it < 8; it++) {
        int n = it * 32 + lane;
        float ar[8];
#pragma unroll
        for (int s = 0; s < 8; s++) ar[s] = as_[n][s];
#pragma unroll
        for (int j = 0; j < 8; j++) {
            float vv = vb[(size_t)(w * 8 + j) * N + n];
#pragma unroll
            for (int s = 0; s < 8; s++) acc[j][s] = fmaf(vv, ar[s], acc[j][s]);
        }
    }
#pragma unroll
    for (int j = 0; j < 8; j++) {
#pragma unroll
        for (int s = 0; s < 8; s++) {
            float v = acc[j][s];
#pragma unroll
            for (int o = 16; o > 0; o >>= 1) v += __shfl_xor_sync(~0u, v, o);
            if (lane == s)
                atomicAdd(&g_upd[b * 512 + s * 64 + w * 8 + j], v);
        }
    }
}

// =====================================================================
// K4: GRU + residual MLP -> new slots, then LN(ns)+q for next iteration.
// Divides update numerators by colsum; zeroes colsum/upd for next iter.
// grid B, 256 threads.
// =====================================================================
__global__ __launch_bounds__(256) void k_gru_mlp_q(
    const float* __restrict__ wih, const float* __restrict__ whh,
    const float* __restrict__ bih, const float* __restrict__ bhh,
    const float* __restrict__ nmw, const float* __restrict__ nmb,
    const float* __restrict__ mw1, const float* __restrict__ mb1,
    const float* __restrict__ mw2, const float* __restrict__ mb2,
    const float* __restrict__ Wq,
    const float* __restrict__ nsw, const float* __restrict__ nsb)
{
    __shared__ float us[8][64], sp[8][64];
    __shared__ float gih[8][192], ghh[8][192];
    __shared__ float ws1[32][65], ws2[32][65];
    __shared__ float lns[8][64];
    __shared__ float h1s[8][128];

    const int t = threadIdx.x, b = blockIdx.x;
    const int w = t >> 5, lane = t & 31;

    {
        float cs0 = g_colsum[b * 8 + (t >> 6)];
        float cs1 = g_colsum[b * 8 + ((t + 256) >> 6)];
        ((float*)us)[t]       = g_upd[b * 512 + t] / cs0;
        ((float*)us)[t + 256] = g_upd[b * 512 + t + 256] / cs1;
    }
    ((float*)sp)[t]       = g_slots[b * 512 + t];
    ((float*)sp)[t + 256] = g_slots[b * 512 + t + 256];
    __syncthreads();
    // reset accumulators for next iteration
    if (t < 8) g_colsum[b * 8 + t] = 0.f;
    g_upd[b * 512 + t] = 0.f;
    g_upd[b * 512 + t + 256] = 0.f;

    // gi / gh : 6 chunks of 32 outputs
    for (int c = 0; c < 6; c++) {
        const int o0 = c * 32;
        __syncthreads();
#pragma unroll
        for (int j = 0; j < 8; j++) {
            int e = t + 256 * j;
            int oo = e >> 6, din = e & 63;
            ws1[oo][din] = wih[(o0 + oo) * 64 + din];
            ws2[oo][din] = whh[(o0 + oo) * 64 + din];
        }
        __syncthreads();
        float a = __ldg(&bih[o0 + lane]);
        float h = __ldg(&bhh[o0 + lane]);
#pragma unroll
        for (int din = 0; din < 64; din++) {
            a = fmaf(us[w][din], ws1[lane][din], a);
            h = fmaf(sp[w][din], ws2[lane][din], h);
        }
        gih[w][o0 + lane] = a;
        ghh[w][o0 + lane] = h;
    }
    __syncthreads();

    // gates (torch order r,z,n)
    float sn0, sn1;
    {
        int dd = lane;
        float r = 1.f / (1.f + expf(-(gih[w][dd] + ghh[w][dd])));
        float z = 1.f / (1.f + expf(-(gih[w][64 + dd] + ghh[w][64 + dd])));
        float nn = tanhf(gih[w][128 + dd] + r * ghh[w][128 + dd]);
        sn0 = (1.f - z) * nn + z * sp[w][dd];
    }
    {
        int dd = lane + 32;
        float r = 1.f / (1.f + expf(-(gih[w][dd] + ghh[w][dd])));
        float z = 1.f / (1.f + expf(-(gih[w][64 + dd] + ghh[w][64 + dd])));
        float nn = tanhf(gih[w][128 + dd] + r * ghh[w][128 + dd]);
        sn1 = (1.f - z) * nn + z * sp[w][dd];
    }
    // LN(nm) of GRU output
    float s = sn0 + sn1, q2 = sn0 * sn0 + sn1 * sn1;
#pragma unroll
    for (int o = 16; o > 0; o >>= 1) {
        s  += __shfl_xor_sync(~0u, s, o);
        q2 += __shfl_xor_sync(~0u, q2, o);
    }
    float mu = s * (1.f / 64.f);
    float rs = rsqrtf(q2 * (1.f / 64.f) - mu * mu + LN_EPS);
    lns[w][lane]      = (sn0 - mu) * rs * __ldg(&nmw[lane])      + __ldg(&nmb[lane]);
    lns[w][lane + 32] = (sn1 - mu) * rs * __ldg(&nmw[lane + 32]) + __ldg(&nmb[lane + 32]);
    __syncthreads();

    // MLP layer 1: 4 chunks of 32 hidden units
    for (int c = 0; c < 4; c++) {
        const int m0 = c * 32;
        __syncthreads();
#pragma unroll
        for (int j = 0; j < 8; j++) {
            int e = t + 256 * j;
            int mm = e >> 6, din = e & 63;
            ws1[mm][din] = mw1[(m0 + mm) * 64 + din];
        }
        __syncthreads();
        float a = __ldg(&mb1[m0 + lane]);
#pragma unroll
        for (int din = 0; din < 64; din++)
            a = fmaf(lns[w][din], ws1[lane][din], a);
        h1s[w][m0 + lane] = fmaxf(a, 0.f);
    }
    __syncthreads();

    // MLP layer 2
    float out0 = __ldg(&mb2[lane]);
    float out1 = __ldg(&mb2[lane + 32]);
    for (int c = 0; c < 4; c++) {
        const int m0 = c * 32;
        __syncthreads();
#pragma unroll
        for (int j = 0; j < 8; j++) {
            int e = t + 256 * j;               // d = e>>5 (0..63), mm = e&31
            ws1[e & 31][e >> 5] = mw2[(e >> 5) * 128 + m0 + (e & 31)];
        }
        __syncthreads();
#pragma unroll
        for (int mm = 0; mm < 32; mm++) {
            float hv = h1s[w][m0 + mm];
            out0 = fmaf(hv, ws1[mm][lane], out0);
            out1 = fmaf(hv, ws1[mm][lane + 32], out1);
        }
    }
    float fs0 = sn0 + out0, fs1 = sn1 + out1;
    g_slots[b * 512 + w * 64 + lane]      = fs0;
    g_slots[b * 512 + w * 64 + lane + 32] = fs1;

    // ---- q for NEXT iteration: LN(ns) + @ Wq^T * scale ----
    float s2 = fs0 + fs1, qq = fs0 * fs0 + fs1 * fs1;
#pragma unroll
    for (int o = 16; o > 0; o >>= 1) {
        s2 += __shfl_xor_sync(~0u, s2, o);
        qq += __shfl_xor_sync(~0u, qq, o);
    }
    float mu3 = s2 * (1.f / 64.f);
    float rs3 = rsqrtf(qq * (1.f / 64.f) - mu3 * mu3 + LN_EPS);
    __syncthreads();   // before lns reuse
    lns[w][lane]      = (fs0 - mu3) * rs3 * __ldg(&nsw[lane])      + __ldg(&nsb[lane]);
    lns[w][lane + 32] = (fs1 - mu3) * rs3 * __ldg(&nsw[lane + 32]) + __ldg(&nsb[lane + 32]);

    for (int c = 0; c < 64; c += 32) {
        __syncthreads();
#pragma unroll
        for (int j = 0; j < 8; j++) {
            int e = t + 256 * j;
            ws1[e >> 6][e & 63] = Wq[(c + (e >> 6)) * 64 + (e & 63)];
        }
        __syncthreads();
        float a = 0.f;
#pragma unroll
        for (int din = 0; din < 64; din++)
            a = fmaf(lns[w][din], ws1[lane][din], a);
        g_q[b * 512 + w * 64 + c + lane] = a * 0.125f;
    }
}

// =====================================================================
// K5: fused = mean(slots, axis=S); out = fused @ head_w^T + head_b
// grid B, 64 threads.
// =====================================================================
__global__ void k_head(const float* __restrict__ hw_, const float* __restrict__ hb_,
                       float* __restrict__ out)
{
    __shared__ float f[64];
    const int t = threadIdx.x, b = blockIdx.x;
    float s = 0.f;
#pragma unroll
    for (int ss = 0; ss < 8; ss++) s += g_slots[b * 512 + ss * 64 + t];
    f[t] = s * (1.f / 8.f);
    __syncthreads();
    if (t < NC) {
        float a = hb_[t];
#pragma unroll
        for (int d = 0; d < 64; d++) a = fmaf(f[d], hw_[t * 64 + d], a);
        out[b * NC + t] = a;
    }
}

// =====================================================================
extern "C" void kernel_launch(void* const* d_in, const int* in_sizes, int n_in,
                              void* d_out, int out_size)
{
    const float* x1   = (const float*)d_in[0];
    const float* x2   = (const float*)d_in[1];
    const float* c1w  = (const float*)d_in[2];
    const float* c1b  = (const float*)d_in[3];
    const float* c2w  = (const float*)d_in[4];
    const float* c2b  = (const float*)d_in[5];
    const float* nw   = (const float*)d_in[6];
    const float* nb   = (const float*)d_in[7];
    const float* niw  = (const float*)d_in[8];
    const float* nib  = (const float*)d_in[9];
    const float* nsw  = (const float*)d_in[10];
    const float* nsb  = (const float*)d_in[11];
    const float* nmw  = (const float*)d_in[12];
    const float* nmb  = (const float*)d_in[13];
    const float* smu  = (const float*)d_in[14];
    const float* sls  = (const float*)d_in[15];
    const float* Wq   = (const float*)d_in[16];
    const float* Wk   = (const float*)d_in[17];
    const float* Wv   = (const float*)d_in[18];
    const float* wih  = (const float*)d_in[19];
    const float* whh  = (const float*)d_in[20];
    const float* bih  = (const float*)d_in[21];
    const float* bhh  = (const float*)d_in[22];
    const float* mw1  = (const float*)d_in[23];
    const float* mb1  = (const float*)d_in[24];
    const float* mw2  = (const float*)d_in[25];
    const float* mb2  = (const float*)d_in[26];
    const float* hw_  = (const float*)d_in[27];
    const float* hb_  = (const float*)d_in[28];
    const float* noise= (const float*)d_in[29];
    float* out = (float*)d_out;

    k_conv_kv<<<B * 16, 256>>>(x1, x2, c1w, c1b, c2w, c2b, nw, nb, niw, nib, Wk, Wv);
    k_init_q<<<B, 256>>>(smu, sls, noise, Wq, nsw, nsb);

    for (int it = 0; it < 3; it++) {
        k_attn_upd<<<B * 8, 256>>>();
        k_gru_mlp_q<<<B, 256>>>(wih, whh, bih, bhh, nmw, nmb,
                                mw1, mb1, mw2, mb2, Wq, nsw, nsb);
    }
    k_head<<<B, 64>>>(hw_, hb_, out);
}

// round 14
// speedup vs baseline: 1.3180x; 1.2754x over previous
#include <cuda_runtime.h>
#include <cuda_bf16.h>
#include <math.h>

constexpr int B  = 128;
constexpr int C  = 256;
constexpr int HW = 1024;
constexpr int N  = 2048;
constexpr int D  = 64;
constexpr int S  = 8;
constexpr int MH = 128;
constexpr int NC = 15;
constexpr float LN_EPS = 1e-5f;
constexpr float SA_EPS = 1e-8f;

__device__ float g_k  [(size_t)B * D * N];
__device__ float g_v  [(size_t)B * D * N];
__device__ float g_slots[B * S * D];
__device__ float g_q    [B * S * D];
__device__ float g_colsum[B * S];
__device__ float g_upd  [B * S * D];

__device__ __forceinline__ void ldsm4(unsigned& r0, unsigned& r1, unsigned& r2, unsigned& r3, unsigned a) {
    asm volatile("ldmatrix.sync.aligned.m8n8.x4.shared.b16 {%0,%1,%2,%3},[%4];"
                 : "=r"(r0), "=r"(r1), "=r"(r2), "=r"(r3) : "r"(a));
}
__device__ __forceinline__ void ldsm4t(unsigned& r0, unsigned& r1, unsigned& r2, unsigned& r3, unsigned a) {
    asm volatile("ldmatrix.sync.aligned.m8n8.x4.trans.shared.b16 {%0,%1,%2,%3},[%4];"
                 : "=r"(r0), "=r"(r1), "=r"(r2), "=r"(r3) : "r"(a));
}
__device__ __forceinline__ void mma16816(float* c, const unsigned* a, const unsigned* b) {
    asm volatile("mma.sync.aligned.m16n8k16.row.col.f32.bf16.bf16.f32 "
                 "{%0,%1,%2,%3},{%4,%5,%6,%7},{%8,%9},{%0,%1,%2,%3};"
                 : "+f"(c[0]), "+f"(c[1]), "+f"(c[2]), "+f"(c[3])
                 : "r"(a[0]), "r"(a[1]), "r"(a[2]), "r"(a[3]), "r"(b[0]), "r"(b[1]));
}
__device__ __forceinline__ unsigned pk2(__nv_bfloat16 a, __nv_bfloat16 b) {
    return (unsigned)__bfloat16_as_ushort(a) | ((unsigned)__bfloat16_as_ushort(b) << 16);
}
__device__ __forceinline__ void split4(float4 v, uint2& h, uint2& l) {
    __nv_bfloat16 h0 = __float2bfloat16_rn(v.x), h1 = __float2bfloat16_rn(v.y);
    __nv_bfloat16 h2 = __float2bfloat16_rn(v.z), h3 = __float2bfloat16_rn(v.w);
    __nv_bfloat16 l0 = __float2bfloat16_rn(v.x - __bfloat162float(h0));
    __nv_bfloat16 l1 = __float2bfloat16_rn(v.y - __bfloat162float(h1));
    __nv_bfloat16 l2 = __float2bfloat16_rn(v.z - __bfloat162float(h2));
    __nv_bfloat16 l3 = __float2bfloat16_rn(v.w - __bfloat162float(h3));
    h.x = pk2(h0, h1); h.y = pk2(h2, h3);
    l.x = pk2(l0, l1); l.y = pk2(l2, l3);
}
__device__ __forceinline__ void split1(float v, unsigned short& h, unsigned short& l) {
    __nv_bfloat16 hb = __float2bfloat16_rn(v);
    __nv_bfloat16 lb = __float2bfloat16_rn(v - __bfloat162float(hb));
    h = __bfloat16_as_ushort(hb); l = __bfloat16_as_ushort(lb);
}

constexpr int P_XH = 0, P_XL = 8192, P_WH = 16384, P_WL = 21504;
constexpr int P_TH = 0, P_TL = 18432, P_W2H = 36864, P_W2L = 41984;
constexpr int P_CB = 47104, P_NW = 47360, P_NB = 47616, P_IW = 47872, P_IB = 48128;
constexpr int POOL_BYTES = 48384;

// =====================================================================
// K1: conv+bias+LN+LN+kv projection on tensor cores (bf16 3-term split)
// grid 2048, 256 threads; CTA = 128 tokens; warp w = tokens 16w..16w+15.
// =====================================================================
__global__ __launch_bounds__(256) void k_conv_mma(
    const float* __restrict__ x1, const float* __restrict__ x2,
    const float* __restrict__ cw1, const float* __restrict__ cb1,
    const float* __restrict__ cw2, const float* __restrict__ cb2,
    const float* __restrict__ nw,  const float* __restrict__ nb,
    const float* __restrict__ niw, const float* __restrict__ nib,
    const float* __restrict__ Wk,  const float* __restrict__ Wv)
{
    __shared__ __align__(16) char pool[POOL_BYTES];
    const unsigned sb = (unsigned)__cvta_generic_to_shared(pool);

    const int t = threadIdx.x, w = t >> 5, lane = t & 31;
    const int cid = blockIdx.x, b = cid >> 4, r4 = cid & 15;
    const int conv = r4 >> 3, tile = r4 & 7, hw0 = tile * 128;

    const float* x    = (conv ? x2 : x1) + (size_t)b * C * HW + hw0;
    const float* wc   = conv ? cw2 : cw1;
    const float* bias = conv ? cb2 : cb1;

    if (t < 64) {
        ((float*)(pool + P_CB))[t] = bias[t];
        ((float*)(pool + P_NW))[t] = nw[t];
        ((float*)(pool + P_NB))[t] = nb[t];
        ((float*)(pool + P_IW))[t] = niw[t];
        ((float*)(pool + P_IB))[t] = nib[t];
    }

    float acc[8][4];
#pragma unroll
    for (int nt = 0; nt < 8; nt++) { acc[nt][0] = acc[nt][1] = acc[nt][2] = acc[nt][3] = 0.f; }

    const int g = lane >> 3, l7 = lane & 7;
    const float4* x4 = (const float4*)x;

    for (int ch = 0; ch < 8; ch++) {
        const int c0 = ch * 32;
        __syncthreads();
#pragma unroll
        for (int j = 0; j < 4; j++) {
            int e = t + 256 * j;
            int c = e >> 5, tg = e & 31;
            float4 v = x4[(size_t)(c0 + c) * 256 + tg];
            uint2 h, l; split4(v, h, l);
            unsigned off = c * 256 + ((tg * 8) ^ ((c & 7) << 4));
            *(uint2*)(pool + P_XH + off) = h;
            *(uint2*)(pool + P_XL + off) = l;
        }
#pragma unroll
        for (int j = 0; j < 2; j++) {
            int e = t + 256 * j;
            int d = e >> 3, c4 = e & 7;
            float4 v = *(const float4*)(wc + d * C + c0 + c4 * 4);
            uint2 h, l; split4(v, h, l);
            *(uint2*)(pool + P_WH + d * 80 + c4 * 8) = h;
            *(uint2*)(pool + P_WL + d * 80 + c4 * 8) = l;
        }
        __syncthreads();
#pragma unroll
        for (int ks = 0; ks < 2; ks++) {
            int cl  = ks * 16 + l7 + ((g >> 1) << 3);
            int tkb = 32 * w + ((g & 1) << 4);
            unsigned aaddr = sb + (unsigned)(P_XH + cl * 256 + (tkb ^ ((cl & 7) << 4)));
            unsigned ah[4], al[4];
            ldsm4t(ah[0], ah[1], ah[2], ah[3], aaddr);
            ldsm4t(al[0], al[1], al[2], al[3], aaddr + (P_XL - P_XH));
#pragma unroll
            for (int ntp = 0; ntp < 4; ntp++) {
                int dp = (ntp * 2 + (g >> 1)) * 8 + l7;
                unsigned baddr = sb + (unsigned)(P_WH + dp * 80 + ks * 32 + ((g & 1) << 4));
                unsigned bh[4], bl[4];
                ldsm4(bh[0], bh[1], bh[2], bh[3], baddr);
                ldsm4(bl[0], bl[1], bl[2], bl[3], baddr + (P_WL - P_WH));
                mma16816(acc[2 * ntp],     ah, &bh[0]);
                mma16816(acc[2 * ntp],     ah, &bl[0]);
                mma16816(acc[2 * ntp],     al, &bh[0]);
                mma16816(acc[2 * ntp + 1], ah, &bh[2]);
                mma16816(acc[2 * ntp + 1], ah, &bl[2]);
                mma16816(acc[2 * ntp + 1], al, &bh[2]);
            }
        }
    }
    __syncthreads();

    const float* Pcb = (const float*)(pool + P_CB);
    const float* Pnw = (const float*)(pool + P_NW);
    const float* Pnb = (const float*)(pool + P_NB);
    const float* Piw = (const float*)(pool + P_IW);
    const float* Pib = (const float*)(pool + P_IB);
    const int dlo = (lane & 3) * 2;
    const int r = 16 * w + (lane >> 2);

    float s0 = 0.f, q0 = 0.f, s1 = 0.f, q1 = 0.f;
#pragma unroll
    for (int nt = 0; nt < 8; nt++) {
        float2 cb = *(const float2*)&Pcb[nt * 8 + dlo];
        acc[nt][0] += cb.x; acc[nt][1] += cb.y;
        acc[nt][2] += cb.x; acc[nt][3] += cb.y;
        s0 += acc[nt][0] + acc[nt][1];
        q0 += acc[nt][0] * acc[nt][0] + acc[nt][1] * acc[nt][1];
        s1 += acc[nt][2] + acc[nt][3];
        q1 += acc[nt][2] * acc[nt][2] + acc[nt][3] * acc[nt][3];
    }
#pragma unroll
    for (int o = 1; o <= 2; o <<= 1) {
        s0 += __shfl_xor_sync(~0u, s0, o); q0 += __shfl_xor_sync(~0u, q0, o);
        s1 += __shfl_xor_sync(~0u, s1, o); q1 += __shfl_xor_sync(~0u, q1, o);
    }
    float mu0 = s0 * (1.f / 64.f), rs0 = rsqrtf(q0 * (1.f / 64.f) - mu0 * mu0 + LN_EPS);
    float mu1 = s1 * (1.f / 64.f), rs1 = rsqrtf(q1 * (1.f / 64.f) - mu1 * mu1 + LN_EPS);

    float t0 = 0.f, u0 = 0.f, t1 = 0.f, u1 = 0.f;
#pragma unroll
    for (int nt = 0; nt < 8; nt++) {
        float2 w1 = *(const float2*)&Pnw[nt * 8 + dlo];
        float2 b1 = *(const float2*)&Pnb[nt * 8 + dlo];
        float v0 = (acc[nt][0] - mu0) * rs0 * w1.x + b1.x;
        float v1 = (acc[nt][1] - mu0) * rs0 * w1.y + b1.y;
        float v2 = (acc[nt][2] - mu1) * rs1 * w1.x + b1.x;
        float v3 = (acc[nt][3] - mu1) * rs1 * w1.y + b1.y;
        acc[nt][0] = v0; acc[nt][1] = v1; acc[nt][2] = v2; acc[nt][3] = v3;
        t0 += v0 + v1; u0 += v0 * v0 + v1 * v1;
        t1 += v2 + v3; u1 += v2 * v2 + v3 * v3;
    }
#pragma unroll
    for (int o = 1; o <= 2; o <<= 1) {
        t0 += __shfl_xor_sync(~0u, t0, o); u0 += __shfl_xor_sync(~0u, u0, o);
        t1 += __shfl_xor_sync(~0u, t1, o); u1 += __shfl_xor_sync(~0u, u1, o);
    }
    float mA = t0 * (1.f / 64.f), rA = rsqrtf(u0 * (1.f / 64.f) - mA * mA + LN_EPS);
    float mB = t1 * (1.f / 64.f), rB = rsqrtf(u1 * (1.f / 64.f) - mB * mB + LN_EPS);

#pragma unroll
    for (int nt = 0; nt < 8; nt++) {
        float2 w2 = *(const float2*)&Piw[nt * 8 + dlo];
        float2 b2 = *(const float2*)&Pib[nt * 8 + dlo];
        float f0 = (acc[nt][0] - mA) * rA * w2.x + b2.x;
        float f1 = (acc[nt][1] - mA) * rA * w2.y + b2.y;
        float f2 = (acc[nt][2] - mB) * rB * w2.x + b2.x;
        float f3 = (acc[nt][3] - mB) * rB * w2.y + b2.y;
        unsigned short h0, l0, h1, l1, h2, l2, h3, l3;
        split1(f0, h0, l0); split1(f1, h1, l1);
        split1(f2, h2, l2); split1(f3, h3, l3);
        int d = nt * 8 + dlo;
        *(unsigned*)(pool + P_TH + r * 144 + d * 2)       = (unsigned)h0 | ((unsigned)h1 << 16);
        *(unsigned*)(pool + P_TL + r * 144 + d * 2)       = (unsigned)l0 | ((unsigned)l1 << 16);
        *(unsigned*)(pool + P_TH + (r + 8) * 144 + d * 2) = (unsigned)h2 | ((unsigned)h3 << 16);
        *(unsigned*)(pool + P_TL + (r + 8) * 144 + d * 2) = (unsigned)l2 | ((unsigned)l3 << 16);
    }

    const int n0 = conv * HW + hw0;
#pragma unroll
    for (int kv = 0; kv < 2; kv++) {
        const float* Wx = kv ? Wv : Wk;
        float ac2[8][4];
#pragma unroll
        for (int nt = 0; nt < 8; nt++) { ac2[nt][0] = ac2[nt][1] = ac2[nt][2] = ac2[nt][3] = 0.f; }

#pragma unroll
        for (int ch = 0; ch < 2; ch++) {
            const int c0 = ch * 32;
            __syncthreads();
#pragma unroll
            for (int j = 0; j < 2; j++) {
                int e = t + 256 * j;
                int dp = e >> 3, c4 = e & 7;
                float4 v = *(const float4*)(Wx + dp * 64 + c0 + c4 * 4);
                uint2 h, l; split4(v, h, l);
                *(uint2*)(pool + P_W2H + dp * 80 + c4 * 8) = h;
                *(uint2*)(pool + P_W2L + dp * 80 + c4 * 8) = l;
            }
            __syncthreads();
#pragma unroll
            for (int ks = 0; ks < 2; ks++) {
                int kk2 = c0 + ks * 16;
                int rr  = 16 * w + l7 + ((g & 1) << 3);
                unsigned aaddr = sb + (unsigned)(P_TH + rr * 144 + kk2 * 2 + ((g >> 1) << 4));
                unsigned ah[4], al[4];
                ldsm4(ah[0], ah[1], ah[2], ah[3], aaddr);
                ldsm4(al[0], al[1], al[2], al[3], aaddr + (P_TL - P_TH));
#pragma unroll
                for (int ntp = 0; ntp < 4; ntp++) {
                    int dp = (ntp * 2 + (g >> 1)) * 8 + l7;
                    unsigned baddr = sb + (unsigned)(P_W2H + dp * 80 + ks * 32 + ((g & 1) << 4));
                    unsigned bh[4], bl[4];
                    ldsm4(bh[0], bh[1], bh[2], bh[3], baddr);
                    ldsm4(bl[0], bl[1], bl[2], bl[3], baddr + (P_W2L - P_W2H));
                    mma16816(ac2[2 * ntp],     ah, &bh[0]);
                    mma16816(ac2[2 * ntp],     ah, &bl[0]);
                    mma16816(ac2[2 * ntp],     al, &bh[0]);
                    mma16816(ac2[2 * ntp + 1], ah, &bh[2]);
                    mma16816(ac2[2 * ntp + 1], ah, &bl[2]);
                    mma16816(ac2[2 * ntp + 1], al, &bh[2]);
                }
            }
        }
        float* gout = (kv ? g_v : g_k) + (size_t)b * D * N + n0;
#pragma unroll
        for (int nt = 0; nt < 8; nt++) {
            int d = nt * 8 + dlo;
            gout[(size_t)d * N + r]           = ac2[nt][0];
            gout[(size_t)(d + 1) * N + r]     = ac2[nt][1];
            gout[(size_t)d * N + r + 8]       = ac2[nt][2];
            gout[(size_t)(d + 1) * N + r + 8] = ac2[nt][3];
        }
    }
}

// ===================== K2: slots init + q(iter0) =====================
__global__ __launch_bounds__(256) void k_init_q(
    const float* __restrict__ mu_, const float* __restrict__ ls,
    const float* __restrict__ noise, const float* __restrict__ Wq,
    const float* __restrict__ nsw, const float* __restrict__ nsb)
{
    __shared__ float ws[32][65];
    __shared__ float lns[8][64];
    const int t = threadIdx.x, b = blockIdx.x;
    const int w = t >> 5, lane = t & 31;

    {
        int d = t & 63;
        g_slots[b * 512 + t]       = mu_[d] + expf(ls[d]) * noise[b * 512 + t];
        g_slots[b * 512 + t + 256] = mu_[d] + expf(ls[d]) * noise[b * 512 + t + 256];
    }
    if (t < 8) g_colsum[b * 8 + t] = 0.f;
    g_upd[b * 512 + t] = 0.f;
    g_upd[b * 512 + t + 256] = 0.f;
    __syncthreads();

    float v0 = g_slots[b * 512 + w * 64 + lane];
    float v1 = g_slots[b * 512 + w * 64 + lane + 32];
    float s = v0 + v1, q2 = v0 * v0 + v1 * v1;
#pragma unroll
    for (int o = 16; o > 0; o >>= 1) {
        s  += __shfl_xor_sync(~0u, s, o);
        q2 += __shfl_xor_sync(~0u, q2, o);
    }
    float mu = s * (1.f / 64.f);
    float rs = rsqrtf(q2 * (1.f / 64.f) - mu * mu + LN_EPS);
    lns[w][lane]      = (v0 - mu) * rs * __ldg(&nsw[lane])      + __ldg(&nsb[lane]);
    lns[w][lane + 32] = (v1 - mu) * rs * __ldg(&nsw[lane + 32]) + __ldg(&nsb[lane + 32]);

    for (int c = 0; c < 64; c += 32) {
        __syncthreads();
#pragma unroll
        for (int j = 0; j < 8; j++) {
            int e = t + 256 * j;
            ws[e >> 6][e & 63] = Wq[(c + (e >> 6)) * 64 + (e & 63)];
        }
        __syncthreads();
        float a = 0.f;
#pragma unroll
        for (int din = 0; din < 64; din++)
            a = fmaf(lns[w][din], ws[lane][din], a);
        g_q[b * 512 + w * 64 + c + lane] = a * 0.125f;
    }
}

// ============ K3: attn softmax + colsum + update numerators ============
__global__ __launch_bounds__(256) void k_attn_upd(void)
{
    __shared__ float qs[512];
    __shared__ float as_[256][9];
    __shared__ float scs[8];
    const int t = threadIdx.x;
    const int b = blockIdx.x >> 3;
    const int n0 = (blockIdx.x & 7) * 256;
    const int w = t >> 5, lane = t & 31;

    if (t < 8) scs[t] = 0.f;
    qs[t] = g_q[b * 512 + t];
    qs[t + 256] = g_q[b * 512 + t + 256];
    __syncthreads();

    const float* kb = g_k + (size_t)b * D * N + n0 + t;
    float lg[8];
#pragma unroll
    for (int s = 0; s < 8; s++) lg[s] = 0.f;
#pragma unroll 8
    for (int d = 0; d < 64; d++) {
        float kv = kb[(size_t)d * N];
#pragma unroll
        for (int s = 0; s < 8; s++) lg[s] = fmaf(kv, qs[s * 64 + d], lg[s]);
    }
    float m = lg[0];
#pragma unroll
    for (int s = 1; s < 8; s++) m = fmaxf(m, lg[s]);
    float sum = 0.f;
#pragma unroll
    for (int s = 0; s < 8; s++) { lg[s] = expf(lg[s] - m); sum += lg[s]; }
    float inv = 1.f / sum;
#pragma unroll
    for (int s = 0; s < 8; s++) {
        lg[s] = lg[s] * inv + SA_EPS;
        as_[t][s] = lg[s];
    }
#pragma unroll
    for (int s = 0; s < 8; s++) {
        float v = lg[s];
#pragma unroll
        for (int o = 16; o > 0; o >>= 1) v += __shfl_xor_sync(~0u, v, o);
        if (lane == 0) atomicAdd(&scs[s], v);
    }
    __syncthreads();
    if (t < 8) atomicAdd(&g_colsum[b * 8 + t], scs[t]);

    float acc[8][8];
#pragma unroll
    for (int j = 0; j < 8; j++)
#pragma unroll
        for (int s = 0; s < 8; s++) acc[j][s] = 0.f;

    const float* vb = g_v + (size_t)b * D * N + n0;
#pragma unroll
    for (int it = 0; it < 8; it++) {
        int n = it * 32 + lane;
        float ar[8];
#pragma unroll
        for (int s = 0; s < 8; s++) ar[s] = as_[n][s];
#pragma unroll
        for (int j = 0; j < 8; j++) {
            float vv = vb[(size_t)(w * 8 + j) * N + n];
#pragma unroll
            for (int s = 0; s < 8; s++) acc[j][s] = fmaf(vv, ar[s], acc[j][s]);
        }
    }
#pragma unroll
    for (int j = 0; j < 8; j++) {
#pragma unroll
        for (int s = 0; s < 8; s++) {
            float v = acc[j][s];
#pragma unroll
            for (int o = 16; o > 0; o >>= 1) v += __shfl_xor_sync(~0u, v, o);
            if (lane == s)
                atomicAdd(&g_upd[b * 512 + s * 64 + w * 8 + j], v);
        }
    }
}

// ============== K4: GRU + MLP + q for next iteration ==============
__global__ __launch_bounds__(256) void k_gru_mlp_q(
    const float* __restrict__ wih, const float* __restrict__ whh,
    const float* __restrict__ bih, const float* __restrict__ bhh,
    const float* __restrict__ nmw, const float* __restrict__ nmb,
    const float* __restrict__ mw1, const float* __restrict__ mb1,
    const float* __restrict__ mw2, const float* __restrict__ mb2,
    const float* __restrict__ Wq,
    const float* __restrict__ nsw, const float* __restrict__ nsb)
{
    __shared__ float us[8][64], sp[8][64];
    __shared__ float gih[8][192], ghh[8][192];
    __shared__ float ws1[32][65], ws2[32][65];
    __shared__ float lns[8][64];
    __shared__ float h1s[8][128];

    const int t = threadIdx.x, b = blockIdx.x;
    const int w = t >> 5, lane = t & 31;

    {
        float cs0 = g_colsum[b * 8 + (t >> 6)];
        float cs1 = g_colsum[b * 8 + ((t + 256) >> 6)];
        ((float*)us)[t]       = g_upd[b * 512 + t] / cs0;
        ((float*)us)[t + 256] = g_upd[b * 512 + t + 256] / cs1;
    }
    ((float*)sp)[t]       = g_slots[b * 512 + t];
    ((float*)sp)[t + 256] = g_slots[b * 512 + t + 256];
    __syncthreads();
    if (t < 8) g_colsum[b * 8 + t] = 0.f;
    g_upd[b * 512 + t] = 0.f;
    g_upd[b * 512 + t + 256] = 0.f;

    for (int c = 0; c < 6; c++) {
        const int o0 = c * 32;
        __syncthreads();
#pragma unroll
        for (int j = 0; j < 8; j++) {
            int e = t + 256 * j;
            int oo = e >> 6, din = e & 63;
            ws1[oo][din] = wih[(o0 + oo) * 64 + din];
            ws2[oo][din] = whh[(o0 + oo) * 64 + din];
        }
        __syncthreads();
        float a = __ldg(&bih[o0 + lane]);
        float h = __ldg(&bhh[o0 + lane]);
#pragma unroll
        for (int din = 0; din < 64; din++) {
            a = fmaf(us[w][din], ws1[lane][din], a);
            h = fmaf(sp[w][din], ws2[lane][din], h);
        }
        gih[w][o0 + lane] = a;
        ghh[w][o0 + lane] = h;
    }
    __syncthreads();

    float sn0, sn1;
    {
        int dd = lane;
        float r = 1.f / (1.f + expf(-(gih[w][dd] + ghh[w][dd])));
        float z = 1.f / (1.f + expf(-(gih[w][64 + dd] + ghh[w][64 + dd])));
        float nn = tanhf(gih[w][128 + dd] + r * ghh[w][128 + dd]);
        sn0 = (1.f - z) * nn + z * sp[w][dd];
    }
    {
        int dd = lane + 32;
        float r = 1.f / (1.f + expf(-(gih[w][dd] + ghh[w][dd])));
        float z = 1.f / (1.f + expf(-(gih[w][64 + dd] + ghh[w][64 + dd])));
        float nn = tanhf(gih[w][128 + dd] + r * ghh[w][128 + dd]);
        sn1 = (1.f - z) * nn + z * sp[w][dd];
    }
    float s = sn0 + sn1, q2 = sn0 * sn0 + sn1 * sn1;
#pragma unroll
    for (int o = 16; o > 0; o >>= 1) {
        s  += __shfl_xor_sync(~0u, s, o);
        q2 += __shfl_xor_sync(~0u, q2, o);
    }
    float mu = s * (1.f / 64.f);
    float rs = rsqrtf(q2 * (1.f / 64.f) - mu * mu + LN_EPS);
    lns[w][lane]      = (sn0 - mu) * rs * __ldg(&nmw[lane])      + __ldg(&nmb[lane]);
    lns[w][lane + 32] = (sn1 - mu) * rs * __ldg(&nmw[lane + 32]) + __ldg(&nmb[lane + 32]);
    __syncthreads();

    for (int c = 0; c < 4; c++) {
        const int m0 = c * 32;
        __syncthreads();
#pragma unroll
        for (int j = 0; j < 8; j++) {
            int e = t + 256 * j;
            int mm = e >> 6, din = e & 63;
            ws1[mm][din] = mw1[(m0 + mm) * 64 + din];
        }
        __syncthreads();
        float a = __ldg(&mb1[m0 + lane]);
#pragma unroll
        for (int din = 0; din < 64; din++)
            a = fmaf(lns[w][din], ws1[lane][din], a);
        h1s[w][m0 + lane] = fmaxf(a, 0.f);
    }
    __syncthreads();

    float out0 = __ldg(&mb2[lane]);
    float out1 = __ldg(&mb2[lane + 32]);
    for (int c = 0; c < 4; c++) {
        const int m0 = c * 32;
        __syncthreads();
#pragma unroll
        for (int j = 0; j < 8; j++) {
            int e = t + 256 * j;
            ws1[e & 31][e >> 5] = mw2[(e >> 5) * 128 + m0 + (e & 31)];
        }
        __syncthreads();
#pragma unroll
        for (int mm = 0; mm < 32; mm++) {
            float hv = h1s[w][m0 + mm];
            out0 = fmaf(hv, ws1[mm][lane], out0);
            out1 = fmaf(hv, ws1[mm][lane + 32], out1);
        }
    }
    float fs0 = sn0 + out0, fs1 = sn1 + out1;
    g_slots[b * 512 + w * 64 + lane]      = fs0;
    g_slots[b * 512 + w * 64 + lane + 32] = fs1;

    float s2 = fs0 + fs1, qq = fs0 * fs0 + fs1 * fs1;
#pragma unroll
    for (int o = 16; o > 0; o >>= 1) {
        s2 += __shfl_xor_sync(~0u, s2, o);
        qq += __shfl_xor_sync(~0u, qq, o);
    }
    float mu3 = s2 * (1.f / 64.f);
    float rs3 = rsqrtf(qq * (1.f / 64.f) - mu3 * mu3 + LN_EPS);
    __syncthreads();
    lns[w][lane]      = (fs0 - mu3) * rs3 * __ldg(&nsw[lane])      + __ldg(&nsb[lane]);
    lns[w][lane + 32] = (fs1 - mu3) * rs3 * __ldg(&nsw[lane + 32]) + __ldg(&nsb[lane + 32]);

    for (int c = 0; c < 64; c += 32) {
        __syncthreads();
#pragma unroll
        for (int j = 0; j < 8; j++) {
            int e = t + 256 * j;
            ws1[e >> 6][e & 63] = Wq[(c + (e >> 6)) * 64 + (e & 63)];
        }
        __syncthreads();
        float a = 0.f;
#pragma unroll
        for (int din = 0; din < 64; din++)
            a = fmaf(lns[w][din], ws1[lane][din], a);
        g_q[b * 512 + w * 64 + c + lane] = a * 0.125f;
    }
}

// ======================= K5: mean + head =======================
__global__ void k_head(const float* __restrict__ hw_, const float* __restrict__ hb_,
                       float* __restrict__ out)
{
    __shared__ float f[64];
    const int t = threadIdx.x, b = blockIdx.x;
    float s = 0.f;
#pragma unroll
    for (int ss = 0; ss < 8; ss++) s += g_slots[b * 512 + ss * 64 + t];
    f[t] = s * (1.f / 8.f);
    __syncthreads();
    if (t < NC) {
        float a = hb_[t];
#pragma unroll
        for (int d = 0; d < 64; d++) a = fmaf(f[d], hw_[t * 64 + d], a);
        out[b * NC + t] = a;
    }
}

extern "C" void kernel_launch(void* const* d_in, const int* in_sizes, int n_in,
                              void* d_out, int out_size)
{
    const float* x1   = (const float*)d_in[0];
    const float* x2   = (const float*)d_in[1];
    const float* c1w  = (const float*)d_in[2];
    const float* c1b  = (const float*)d_in[3];
    const float* c2w  = (const float*)d_in[4];
    const float* c2b  = (const float*)d_in[5];
    const float* nw   = (const float*)d_in[6];
    const float* nb   = (const float*)d_in[7];
    const float* niw  = (const float*)d_in[8];
    const float* nib  = (const float*)d_in[9];
    const float* nsw  = (const float*)d_in[10];
    const float* nsb  = (const float*)d_in[11];
    const float* nmw  = (const float*)d_in[12];
    const float* nmb  = (const float*)d_in[13];
    const float* smu  = (const float*)d_in[14];
    const float* sls  = (const float*)d_in[15];
    const float* Wq   = (const float*)d_in[16];
    const float* Wk   = (const float*)d_in[17];
    const float* Wv   = (const float*)d_in[18];
    const float* wih  = (const float*)d_in[19];
    const float* whh  = (const float*)d_in[20];
    const float* bih  = (const float*)d_in[21];
    const float* bhh  = (const float*)d_in[22];
    const float* mw1  = (const float*)d_in[23];
    const float* mb1  = (const float*)d_in[24];
    const float* mw2  = (const float*)d_in[25];
    const float* mb2  = (const float*)d_in[26];
    const float* hw_  = (const float*)d_in[27];
    const float* hb_  = (const float*)d_in[28];
    const float* noise= (const float*)d_in[29];
    float* out = (float*)d_out;

    k_conv_mma<<<B * 16, 256>>>(x1, x2, c1w, c1b, c2w, c2b, nw, nb, niw, nib, Wk, Wv);
    k_init_q<<<B, 256>>>(smu, sls, noise, Wq, nsw, nsb);

    for (int it = 0; it < 3; it++) {
        k_attn_upd<<<B * 8, 256>>>();
        k_gru_mlp_q<<<B, 256>>>(wih, whh, bih, bhh, nmw, nmb,
                                mw1, mb1, mw2, mb2, Wq, nsw, nsb);
    }
    k_head<<<B, 64>>>(hw_, hb_, out);
}